// round 1
// baseline (speedup 1.0000x reference)
#include <cuda_runtime.h>

// Problem constants
#define BB   8
#define NNN  512
#define FF   256
#define CCH  1024      // 4*FOUT
#define RR   4096      // B*N
#define NMAX 32

// Scratch (device globals; no allocation allowed)
__device__ float g_hpre[RR * CCH];   // concat [self, h1, h2, h3] pre-norm
__device__ float g_yn[RR * FF];      // x @ Wn^T (no bias)
__device__ float g_rnorm[RR];
__device__ float g_sum[CCH];
__device__ float g_sumsq[CCH];
__device__ float g_scale[CCH];
__device__ float g_shift[CCH];

// ---------------------------------------------------------------------------
// K0: zero BN accumulators
// ---------------------------------------------------------------------------
__global__ void k_zero() {
    int i = blockIdx.x * 1024 + threadIdx.x;
    if (i < CCH) g_sum[i] = 0.f;
    else         g_sumsq[i - CCH] = 0.f;
}

// ---------------------------------------------------------------------------
// K1: C[4096,512] = X[4096,256] @ W^T, W = [Wx; Wn] (each [256,256] row-major,
// row = output channel). cols 0..255 -> h_self (+bias bx) into g_hpre[:,0:256],
// cols 256..511 -> g_yn (no bias).
// 64x64 tile, 256 threads, 4x4 per thread.
// ---------------------------------------------------------------------------
__global__ __launch_bounds__(256) void k_gemm(const float* __restrict__ X,
                                              const float* __restrict__ Wx,
                                              const float* __restrict__ bx,
                                              const float* __restrict__ Wn) {
    __shared__ float Xs[32][65];
    __shared__ float Ws[32][65];

    const int t  = threadIdx.x;
    const int m0 = blockIdx.y * 64;
    const int c0 = blockIdx.x * 64;   // 0,64,...,448
    const bool self = (c0 < 256);
    const float* __restrict__ W = self ? (Wx + c0 * 256) : (Wn + (c0 - 256) * 256);

    float acc[4][4];
#pragma unroll
    for (int i = 0; i < 4; i++)
#pragma unroll
        for (int j = 0; j < 4; j++) acc[i][j] = 0.f;

    const int ty = t >> 4, tx = t & 15;

    for (int k0 = 0; k0 < 256; k0 += 32) {
#pragma unroll
        for (int i = 0; i < 2; i++) {
            int f   = t + 256 * i;
            int row = f >> 3;
            int k4  = f & 7;
            float4 xv = *(const float4*)(X + (m0 + row) * 256 + k0 + k4 * 4);
            Xs[k4 * 4 + 0][row] = xv.x; Xs[k4 * 4 + 1][row] = xv.y;
            Xs[k4 * 4 + 2][row] = xv.z; Xs[k4 * 4 + 3][row] = xv.w;
            float4 wv = *(const float4*)(W + row * 256 + k0 + k4 * 4);
            Ws[k4 * 4 + 0][row] = wv.x; Ws[k4 * 4 + 1][row] = wv.y;
            Ws[k4 * 4 + 2][row] = wv.z; Ws[k4 * 4 + 3][row] = wv.w;
        }
        __syncthreads();
#pragma unroll
        for (int kk = 0; kk < 32; kk++) {
            float a[4], b[4];
#pragma unroll
            for (int i = 0; i < 4; i++) a[i] = Xs[kk][ty * 4 + i];
#pragma unroll
            for (int j = 0; j < 4; j++) b[j] = Ws[kk][tx * 4 + j];
#pragma unroll
            for (int i = 0; i < 4; i++)
#pragma unroll
                for (int j = 0; j < 4; j++) acc[i][j] += a[i] * b[j];
        }
        __syncthreads();
    }

    // Epilogue: thread owns 4 contiguous cols -> float4 stores
    const int col0 = c0 + tx * 4;
#pragma unroll
    for (int i = 0; i < 4; i++) {
        int row = m0 + ty * 4 + i;
        float4 v = make_float4(acc[i][0], acc[i][1], acc[i][2], acc[i][3]);
        if (self) {
            v.x += __ldg(bx + col0 + 0);
            v.y += __ldg(bx + col0 + 1);
            v.z += __ldg(bx + col0 + 2);
            v.w += __ldg(bx + col0 + 3);
            *(float4*)(g_hpre + row * CCH + col0) = v;
        } else {
            *(float4*)(g_yn + row * FF + (col0 - 256)) = v;
        }
    }
}

// ---------------------------------------------------------------------------
// K2: gather-mean through shared memory.
// Block = (channel-chunk ct in 0..3, row-tile rt in 0..3, batch b in 0..7).
// smem: y_n[b, all 512 rows, 64 channels] (128KB) + idx tile (48KB).
// h_i[n,c] = (1/32) * sum_k y_n[idx_i[n,k], c] + bn[c]
// ---------------------------------------------------------------------------
__global__ __launch_bounds__(256) void k_gather(const int* __restrict__ i1,
                                                const int* __restrict__ i2,
                                                const int* __restrict__ i3,
                                                const float* __restrict__ bn) {
    extern __shared__ float sm[];
    float4* syn  = (float4*)sm;                 // 512 rows * 16 float4
    int*    sidx = (int*)(sm + 512 * 64);       // [3][128][32]

    const int t  = threadIdx.x;
    const int ct = blockIdx.x;   // 0..3 channel chunk (64 ch)
    const int rt = blockIdx.y;   // 0..3 output-row tile (128 rows)
    const int b  = blockIdx.z;   // 0..7

    const float4* yn4 = (const float4*)g_yn;
#pragma unroll
    for (int i = 0; i < 32; i++) {
        int lin = t + 256 * i;                  // = row*16 + c4
        int row = lin >> 4, c4 = lin & 15;
        syn[lin] = yn4[(b * 512 + row) * 64 + ct * 16 + c4];
    }
#pragma unroll
    for (int i = 0; i < 48; i++) {
        int lin = t + 256 * i;                  // 0..12287
        int s   = lin >> 12;
        int rem = lin & 4095;                   // rl*32 + k
        const int* ip = (s == 0) ? i1 : (s == 1) ? i2 : i3;
        sidx[lin] = ip[rt * 4096 + rem];
    }
    __syncthreads();

    const int cq = t & 15;     // which float4 of the 64-ch chunk
    const int rg = t >> 4;     // 16 rows in flight
    const float4 bias = ((const float4*)bn)[ct * 16 + cq];

    for (int r8 = 0; r8 < 8; r8++) {
        const int rl  = r8 * 16 + rg;
        const int row = b * 512 + rt * 128 + rl;
        for (int s = 0; s < 3; s++) {
            const int* ip = sidx + s * 4096 + rl * 32;
            float4 acc = make_float4(0.f, 0.f, 0.f, 0.f);
#pragma unroll
            for (int k = 0; k < 32; k++) {
                int j = ip[k];
                float4 v = syn[j * 16 + cq];
                acc.x += v.x; acc.y += v.y; acc.z += v.z; acc.w += v.w;
            }
            float4 o;
            o.x = acc.x * (1.f / 32.f) + bias.x;
            o.y = acc.y * (1.f / 32.f) + bias.y;
            o.z = acc.z * (1.f / 32.f) + bias.z;
            o.w = acc.w * (1.f / 32.f) + bias.w;
            ((float4*)g_hpre)[row * 256 + 64 + s * 64 + ct * 16 + cq] = o;
        }
    }
}

// ---------------------------------------------------------------------------
// K3: per-row L2 norm (store 1/max(||h||,eps)) + per-channel BN partial sums
// of relu(h_pre * rnorm). Block = 32 rows; thread t owns channels 4t..4t+3.
// ---------------------------------------------------------------------------
__global__ __launch_bounds__(256) void k_stats() {
    __shared__ float red[9];
    const int t    = threadIdx.x;
    const int lane = t & 31;
    const int w    = t >> 5;

    float cs[4] = {0.f, 0.f, 0.f, 0.f};
    float cq[4] = {0.f, 0.f, 0.f, 0.f};
    const float4* hp4 = (const float4*)g_hpre;

    for (int rl = 0; rl < 32; rl++) {
        const int row = blockIdx.x * 32 + rl;
        float4 v = hp4[row * 256 + t];
        float sq = v.x * v.x + v.y * v.y + v.z * v.z + v.w * v.w;
#pragma unroll
        for (int o = 16; o; o >>= 1) sq += __shfl_xor_sync(0xffffffffu, sq, o);
        if (lane == 0) red[w] = sq;
        __syncthreads();
        if (t == 0) {
            float tot = 0.f;
#pragma unroll
            for (int i = 0; i < 8; i++) tot += red[i];
            float rn = 1.f / fmaxf(sqrtf(tot), 1e-12f);
            red[8] = rn;
            g_rnorm[row] = rn;
        }
        __syncthreads();
        const float rn = red[8];
        float h0 = fmaxf(v.x * rn, 0.f);
        float h1 = fmaxf(v.y * rn, 0.f);
        float h2 = fmaxf(v.z * rn, 0.f);
        float h3 = fmaxf(v.w * rn, 0.f);
        cs[0] += h0; cq[0] += h0 * h0;
        cs[1] += h1; cq[1] += h1 * h1;
        cs[2] += h2; cq[2] += h2 * h2;
        cs[3] += h3; cq[3] += h3 * h3;
    }
#pragma unroll
    for (int i = 0; i < 4; i++) {
        atomicAdd(&g_sum[4 * t + i],   cs[i]);
        atomicAdd(&g_sumsq[4 * t + i], cq[i]);
    }
}

// ---------------------------------------------------------------------------
// K4: finalize BN scale/shift per channel
// ---------------------------------------------------------------------------
__global__ void k_finalize(const float* __restrict__ gamma,
                           const float* __restrict__ beta) {
    int c = threadIdx.x;
    float mean = g_sum[c]   * (1.f / 4096.f);
    float var  = g_sumsq[c] * (1.f / 4096.f) - mean * mean;
    float sc   = gamma[c] * rsqrtf(var + 1e-5f);
    g_scale[c] = sc;
    g_shift[c] = beta[c] - mean * sc;
}

// ---------------------------------------------------------------------------
// K5: out = relu(h_pre * rnorm) * scale + shift. One block per row.
// ---------------------------------------------------------------------------
__global__ __launch_bounds__(256) void k_apply(float* __restrict__ out) {
    const int row = blockIdx.x;
    const int t   = threadIdx.x;
    const float4* hp4 = (const float4*)g_hpre;
    float4 v  = hp4[row * 256 + t];
    float  rn = g_rnorm[row];
    float4 sc = ((const float4*)g_scale)[t];
    float4 sh = ((const float4*)g_shift)[t];
    float4 o;
    o.x = fmaxf(v.x * rn, 0.f) * sc.x + sh.x;
    o.y = fmaxf(v.y * rn, 0.f) * sc.y + sh.y;
    o.z = fmaxf(v.z * rn, 0.f) * sc.z + sh.z;
    o.w = fmaxf(v.w * rn, 0.f) * sc.w + sh.w;
    ((float4*)out)[row * 256 + t] = o;
}

// ---------------------------------------------------------------------------
extern "C" void kernel_launch(void* const* d_in, const int* in_sizes, int n_in,
                              void* d_out, int out_size) {
    const float* x     = (const float*)d_in[0];
    const int*   i1    = (const int*)  d_in[1];
    const int*   i2    = (const int*)  d_in[2];
    const int*   i3    = (const int*)  d_in[3];
    const float* Wx    = (const float*)d_in[4];
    const float* bx    = (const float*)d_in[5];
    const float* Wn    = (const float*)d_in[6];
    const float* bnb   = (const float*)d_in[7];
    const float* gamma = (const float*)d_in[8];
    const float* beta  = (const float*)d_in[9];
    float* out = (float*)d_out;

    cudaFuncSetAttribute(k_gather, cudaFuncAttributeMaxDynamicSharedMemorySize,
                         180224);

    k_zero<<<2, 1024>>>();
    k_gemm<<<dim3(8, 64), 256>>>(x, Wx, bx, Wn);
    k_gather<<<dim3(4, 4, 8), 256, 180224>>>(i1, i2, i3, bnb);
    k_stats<<<128, 256>>>();
    k_finalize<<<1, 1024>>>(gamma, beta);
    k_apply<<<4096, 256>>>(out);
}

// round 2
// speedup vs baseline: 1.1273x; 1.1273x over previous
#include <cuda_runtime.h>

// Problem constants
#define BB   8
#define NNN  512
#define FF   256
#define CCH  1024      // 4*FOUT
#define RR   4096      // B*N
#define NMAX 32

// Scratch (device globals; no allocation allowed)
__device__ float g_hpre[RR * CCH];   // concat [self, h1, h2, h3] pre-norm
__device__ float g_yn[RR * FF];      // x @ Wn^T (no bias)
__device__ float g_rnorm[RR];
__device__ float g_sum[CCH];
__device__ float g_sumsq[CCH];
__device__ float g_scale[CCH];
__device__ float g_shift[CCH];

// ---------------------------------------------------------------------------
// K0: zero BN accumulators
// ---------------------------------------------------------------------------
__global__ void k_zero() {
    int i = blockIdx.x * 1024 + threadIdx.x;
    if (i < CCH) g_sum[i] = 0.f;
    else         g_sumsq[i - CCH] = 0.f;
}

// ---------------------------------------------------------------------------
// K1: C[4096,512] = X[4096,256] @ W^T, W = [Wx; Wn] (each [256,256] row-major,
// row = output channel). cols 0..255 -> h_self (+bias bx) into g_hpre[:,0:256],
// cols 256..511 -> g_yn (no bias).
// 64x64 tile, 256 threads, 4x4 per thread.
// ---------------------------------------------------------------------------
__global__ __launch_bounds__(256) void k_gemm(const float* __restrict__ X,
                                              const float* __restrict__ Wx,
                                              const float* __restrict__ bx,
                                              const float* __restrict__ Wn) {
    __shared__ float Xs[32][65];
    __shared__ float Ws[32][65];

    const int t  = threadIdx.x;
    const int m0 = blockIdx.y * 64;
    const int c0 = blockIdx.x * 64;   // 0,64,...,448
    const bool self = (c0 < 256);
    const float* __restrict__ W = self ? (Wx + c0 * 256) : (Wn + (c0 - 256) * 256);

    float acc[4][4];
#pragma unroll
    for (int i = 0; i < 4; i++)
#pragma unroll
        for (int j = 0; j < 4; j++) acc[i][j] = 0.f;

    const int ty = t >> 4, tx = t & 15;

    for (int k0 = 0; k0 < 256; k0 += 32) {
#pragma unroll
        for (int i = 0; i < 2; i++) {
            int f   = t + 256 * i;
            int row = f >> 3;
            int k4  = f & 7;
            float4 xv = *(const float4*)(X + (m0 + row) * 256 + k0 + k4 * 4);
            Xs[k4 * 4 + 0][row] = xv.x; Xs[k4 * 4 + 1][row] = xv.y;
            Xs[k4 * 4 + 2][row] = xv.z; Xs[k4 * 4 + 3][row] = xv.w;
            float4 wv = *(const float4*)(W + row * 256 + k0 + k4 * 4);
            Ws[k4 * 4 + 0][row] = wv.x; Ws[k4 * 4 + 1][row] = wv.y;
            Ws[k4 * 4 + 2][row] = wv.z; Ws[k4 * 4 + 3][row] = wv.w;
        }
        __syncthreads();
#pragma unroll
        for (int kk = 0; kk < 32; kk++) {
            float a[4], b[4];
#pragma unroll
            for (int i = 0; i < 4; i++) a[i] = Xs[kk][ty * 4 + i];
#pragma unroll
            for (int j = 0; j < 4; j++) b[j] = Ws[kk][tx * 4 + j];
#pragma unroll
            for (int i = 0; i < 4; i++)
#pragma unroll
                for (int j = 0; j < 4; j++) acc[i][j] += a[i] * b[j];
        }
        __syncthreads();
    }

    // Epilogue: thread owns 4 contiguous cols -> float4 stores
    const int col0 = c0 + tx * 4;
#pragma unroll
    for (int i = 0; i < 4; i++) {
        int row = m0 + ty * 4 + i;
        float4 v = make_float4(acc[i][0], acc[i][1], acc[i][2], acc[i][3]);
        if (self) {
            v.x += __ldg(bx + col0 + 0);
            v.y += __ldg(bx + col0 + 1);
            v.z += __ldg(bx + col0 + 2);
            v.w += __ldg(bx + col0 + 3);
            *(float4*)(g_hpre + row * CCH + col0) = v;
        } else {
            *(float4*)(g_yn + row * FF + (col0 - 256)) = v;
        }
    }
}

// ---------------------------------------------------------------------------
// K2: gather-mean through shared memory.
// Block = (channel-chunk ct in 0..3, row-tile rt in 0..3, batch b in 0..7).
// smem: y_n[b, all 512 rows, 64 channels] (128KB) + idx tile (48KB).
// h_i[n,c] = (1/32) * sum_k y_n[idx_i[n,k], c] + bn[c]
// ---------------------------------------------------------------------------
__global__ __launch_bounds__(256) void k_gather(const int* __restrict__ i1,
                                                const int* __restrict__ i2,
                                                const int* __restrict__ i3,
                                                const float* __restrict__ bn) {
    extern __shared__ float sm[];
    float4* syn  = (float4*)sm;                 // 512 rows * 16 float4
    int*    sidx = (int*)(sm + 512 * 64);       // [3][128][32]

    const int t  = threadIdx.x;
    const int ct = blockIdx.x;   // 0..3 channel chunk (64 ch)
    const int rt = blockIdx.y;   // 0..3 output-row tile (128 rows)
    const int b  = blockIdx.z;   // 0..7

    const float4* yn4 = (const float4*)g_yn;
#pragma unroll
    for (int i = 0; i < 32; i++) {
        int lin = t + 256 * i;                  // = row*16 + c4
        int row = lin >> 4, c4 = lin & 15;
        syn[lin] = yn4[(b * 512 + row) * 64 + ct * 16 + c4];
    }
#pragma unroll
    for (int i = 0; i < 48; i++) {
        int lin = t + 256 * i;                  // 0..12287
        int s   = lin >> 12;
        int rem = lin & 4095;                   // rl*32 + k
        const int* ip = (s == 0) ? i1 : (s == 1) ? i2 : i3;
        sidx[lin] = ip[rt * 4096 + rem];
    }
    __syncthreads();

    const int cq = t & 15;     // which float4 of the 64-ch chunk
    const int rg = t >> 4;     // 16 rows in flight
    const float4 bias = ((const float4*)bn)[ct * 16 + cq];

    for (int r8 = 0; r8 < 8; r8++) {
        const int rl  = r8 * 16 + rg;
        const int row = b * 512 + rt * 128 + rl;
        for (int s = 0; s < 3; s++) {
            const int* ip = sidx + s * 4096 + rl * 32;
            float4 acc = make_float4(0.f, 0.f, 0.f, 0.f);
#pragma unroll
            for (int k = 0; k < 32; k++) {
                int j = ip[k];
                float4 v = syn[j * 16 + cq];
                acc.x += v.x; acc.y += v.y; acc.z += v.z; acc.w += v.w;
            }
            float4 o;
            o.x = acc.x * (1.f / 32.f) + bias.x;
            o.y = acc.y * (1.f / 32.f) + bias.y;
            o.z = acc.z * (1.f / 32.f) + bias.z;
            o.w = acc.w * (1.f / 32.f) + bias.w;
            ((float4*)g_hpre)[row * 256 + 64 + s * 64 + ct * 16 + cq] = o;
        }
    }
}

// ---------------------------------------------------------------------------
// K3: per-row L2 norm + per-channel BN partial sums, barrier-free main loop.
// One warp per row (8 rows per warp, 64 blocks x 8 warps).
// Lane owns 8 float4 positions (lane + 32*j) -> 32 fixed channels; BN sums
// accumulate in registers, reduced via smem atomics once per block.
// ---------------------------------------------------------------------------
__global__ __launch_bounds__(256) void k_stats() {
    __shared__ float ssum[CCH];
    __shared__ float ssq[CCH];
    const int t    = threadIdx.x;
    const int lane = t & 31;
    const int w    = t >> 5;

    for (int i = t; i < CCH; i += 256) { ssum[i] = 0.f; ssq[i] = 0.f; }
    __syncthreads();

    float4 cs[8], cq[8];
#pragma unroll
    for (int j = 0; j < 8; j++) {
        cs[j] = make_float4(0.f, 0.f, 0.f, 0.f);
        cq[j] = make_float4(0.f, 0.f, 0.f, 0.f);
    }

    const float4* hp4 = (const float4*)g_hpre;
#pragma unroll 1
    for (int ri = 0; ri < 8; ri++) {
        const int row = blockIdx.x * 64 + ri * 8 + w;
        const float4* rp = hp4 + row * 256;
        float4 v[8];
        float sq = 0.f;
#pragma unroll
        for (int j = 0; j < 8; j++) {
            v[j] = rp[lane + 32 * j];
            sq += v[j].x * v[j].x + v[j].y * v[j].y
                + v[j].z * v[j].z + v[j].w * v[j].w;
        }
#pragma unroll
        for (int o = 16; o; o >>= 1) sq += __shfl_xor_sync(0xffffffffu, sq, o);
        const float rn = 1.f / fmaxf(sqrtf(sq), 1e-12f);
        if (lane == 0) g_rnorm[row] = rn;
#pragma unroll
        for (int j = 0; j < 8; j++) {
            float h0 = fmaxf(v[j].x * rn, 0.f);
            float h1 = fmaxf(v[j].y * rn, 0.f);
            float h2 = fmaxf(v[j].z * rn, 0.f);
            float h3 = fmaxf(v[j].w * rn, 0.f);
            cs[j].x += h0; cq[j].x += h0 * h0;
            cs[j].y += h1; cq[j].y += h1 * h1;
            cs[j].z += h2; cq[j].z += h2 * h2;
            cs[j].w += h3; cq[j].w += h3 * h3;
        }
    }

    // reduce 8 warps' register accumulators via shared atomics
#pragma unroll
    for (int j = 0; j < 8; j++) {
        const int c = 4 * (lane + 32 * j);
        atomicAdd(&ssum[c + 0], cs[j].x);
        atomicAdd(&ssum[c + 1], cs[j].y);
        atomicAdd(&ssum[c + 2], cs[j].z);
        atomicAdd(&ssum[c + 3], cs[j].w);
        atomicAdd(&ssq [c + 0], cq[j].x);
        atomicAdd(&ssq [c + 1], cq[j].y);
        atomicAdd(&ssq [c + 2], cq[j].z);
        atomicAdd(&ssq [c + 3], cq[j].w);
    }
    __syncthreads();

    for (int i = t; i < CCH; i += 256) {
        atomicAdd(&g_sum[i],   ssum[i]);
        atomicAdd(&g_sumsq[i], ssq[i]);
    }
}

// ---------------------------------------------------------------------------
// K4: finalize BN scale/shift per channel
// ---------------------------------------------------------------------------
__global__ void k_finalize(const float* __restrict__ gamma,
                           const float* __restrict__ beta) {
    int c = threadIdx.x;
    float mean = g_sum[c]   * (1.f / 4096.f);
    float var  = g_sumsq[c] * (1.f / 4096.f) - mean * mean;
    float sc   = gamma[c] * rsqrtf(var + 1e-5f);
    g_scale[c] = sc;
    g_shift[c] = beta[c] - mean * sc;
}

// ---------------------------------------------------------------------------
// K5: out = relu(h_pre * rnorm) * scale + shift. One block per row.
// ---------------------------------------------------------------------------
__global__ __launch_bounds__(256) void k_apply(float* __restrict__ out) {
    const int row = blockIdx.x;
    const int t   = threadIdx.x;
    const float4* hp4 = (const float4*)g_hpre;
    float4 v  = hp4[row * 256 + t];
    float  rn = g_rnorm[row];
    float4 sc = ((const float4*)g_scale)[t];
    float4 sh = ((const float4*)g_shift)[t];
    float4 o;
    o.x = fmaxf(v.x * rn, 0.f) * sc.x + sh.x;
    o.y = fmaxf(v.y * rn, 0.f) * sc.y + sh.y;
    o.z = fmaxf(v.z * rn, 0.f) * sc.z + sh.z;
    o.w = fmaxf(v.w * rn, 0.f) * sc.w + sh.w;
    ((float4*)out)[row * 256 + t] = o;
}

// ---------------------------------------------------------------------------
extern "C" void kernel_launch(void* const* d_in, const int* in_sizes, int n_in,
                              void* d_out, int out_size) {
    const float* x     = (const float*)d_in[0];
    const int*   i1    = (const int*)  d_in[1];
    const int*   i2    = (const int*)  d_in[2];
    const int*   i3    = (const int*)  d_in[3];
    const float* Wx    = (const float*)d_in[4];
    const float* bx    = (const float*)d_in[5];
    const float* Wn    = (const float*)d_in[6];
    const float* bnb   = (const float*)d_in[7];
    const float* gamma = (const float*)d_in[8];
    const float* beta  = (const float*)d_in[9];
    float* out = (float*)d_out;

    cudaFuncSetAttribute(k_gather, cudaFuncAttributeMaxDynamicSharedMemorySize,
                         180224);

    k_zero<<<2, 1024>>>();
    k_gemm<<<dim3(8, 64), 256>>>(x, Wx, bx, Wn);
    k_gather<<<dim3(4, 4, 8), 256, 180224>>>(i1, i2, i3, bnb);
    k_stats<<<64, 256>>>();
    k_finalize<<<1, 1024>>>(gamma, beta);
    k_apply<<<4096, 256>>>(out);
}

// round 3
// speedup vs baseline: 1.7794x; 1.5784x over previous
#include <cuda_runtime.h>
#include <cuda_bf16.h>
#include <cstdint>

// Problem constants
#define CCH  1024      // 4*FOUT
#define RR   4096      // B*N
#define FF   256

// Scratch (device globals; no allocation allowed)
__device__ float g_hpre[RR * CCH];   // concat [self, h1, h2, h3] pre-norm
__device__ float g_yn[RR * FF];      // x @ Wn^T (no bias)
__device__ float g_rnorm[RR];
__device__ float g_sum[CCH];
__device__ float g_sumsq[CCH];
__device__ float g_scale[CCH];
__device__ float g_shift[CCH];

// ---------------------------------------------------------------------------
// K0: zero BN accumulators
// ---------------------------------------------------------------------------
__global__ void k_zero() {
    int i = blockIdx.x * 1024 + threadIdx.x;
    if (i < CCH) g_sum[i] = 0.f;
    else         g_sumsq[i - CCH] = 0.f;
}

// ---------------------------------------------------------------------------
// MMA helpers (bf16 m16n8k16, fp32 accum)
// ---------------------------------------------------------------------------
__device__ __forceinline__ void mma16816(float c[4], uint32_t a0, uint32_t a1,
                                         uint32_t a2, uint32_t a3,
                                         uint32_t b0, uint32_t b1) {
    asm volatile(
        "mma.sync.aligned.m16n8k16.row.col.f32.bf16.bf16.f32 "
        "{%0,%1,%2,%3}, {%4,%5,%6,%7}, {%8,%9}, {%0,%1,%2,%3};"
        : "+f"(c[0]), "+f"(c[1]), "+f"(c[2]), "+f"(c[3])
        : "r"(a0), "r"(a1), "r"(a2), "r"(a3), "r"(b0), "r"(b1));
}

__device__ __forceinline__ void ldsm4(uint32_t r[4], uint32_t addr) {
    asm volatile("ldmatrix.sync.aligned.m8n8.x4.shared.b16 {%0,%1,%2,%3}, [%4];"
                 : "=r"(r[0]), "=r"(r[1]), "=r"(r[2]), "=r"(r[3]) : "r"(addr));
}

__device__ __forceinline__ uint32_t pack_bf16(float a, float b) {
    __nv_bfloat162 t = __halves2bfloat162(__float2bfloat16_rn(a),
                                          __float2bfloat16_rn(b));
    return *reinterpret_cast<uint32_t*>(&t);
}

// split fp32 float4 -> hi pair-packed (2 regs) and lo pair-packed (2 regs)
__device__ __forceinline__ void split4(float4 v, uint2& hi, uint2& lo) {
    float hx = __bfloat162float(__float2bfloat16_rn(v.x));
    float hy = __bfloat162float(__float2bfloat16_rn(v.y));
    float hz = __bfloat162float(__float2bfloat16_rn(v.z));
    float hw = __bfloat162float(__float2bfloat16_rn(v.w));
    hi.x = pack_bf16(v.x, v.y);
    hi.y = pack_bf16(v.z, v.w);
    lo.x = pack_bf16(v.x - hx, v.y - hy);
    lo.y = pack_bf16(v.z - hz, v.w - hw);
}

// ---------------------------------------------------------------------------
// K1: C[4096,512] = X[4096,256] @ W^T via split-bf16 tensor-core MMA.
// W = [Wx ; Wn]. cols 0..255 -> g_hpre[:,0:256] (+bias), 256..511 -> g_yn.
// CTA tile 128(M) x 64(N), 8 warps in 4x2, warp tile 32x32.
// smem (dynamic 48KB): Ahi[128][64]bf16, Alo, Bhi[64][64]bf16, Blo,
// all with 16B-granularity xor swizzle: unit' = unit ^ (row & 7).
// ---------------------------------------------------------------------------
__global__ __launch_bounds__(256) void k_gemm(const float* __restrict__ X,
                                              const float* __restrict__ Wx,
                                              const float* __restrict__ bx,
                                              const float* __restrict__ Wn) {
    extern __shared__ uint8_t sm[];
    const uint32_t AHI = 0, ALO = 16384, BHI = 32768, BLO = 40960;
    const uint32_t sbase = (uint32_t)__cvta_generic_to_shared(sm);

    const int t  = threadIdx.x;
    const int m0 = blockIdx.y * 128;
    const int c0 = blockIdx.x * 64;
    const bool self = (c0 < 256);
    const float* __restrict__ W = self ? (Wx + c0 * 256) : (Wn + (c0 - 256) * 256);

    const int w    = t >> 5;
    const int lane = t & 31;
    const int wm   = (w & 3) * 32;
    const int wn   = (w >> 2) * 32;

    float acc[2][4][4];
#pragma unroll
    for (int mi = 0; mi < 2; mi++)
#pragma unroll
        for (int nf = 0; nf < 4; nf++)
#pragma unroll
            for (int r = 0; r < 4; r++) acc[mi][nf][r] = 0.f;

    // precompute ldmatrix lane geometry
    const int lm  = lane >> 3;        // matrix id 0..3
    const int lr  = lane & 7;         // row within 8

    for (int kc = 0; kc < 256; kc += 64) {
        // ---- load X tile [128 rows x 64 k] fp32, split to bf16 hi/lo ----
#pragma unroll
        for (int i = 0; i < 8; i++) {
            int lin = t + 256 * i;            // 0..2047
            int row = lin >> 4;               // 0..127
            int k4  = lin & 15;               // float4 index within 64 k
            float4 v = *(const float4*)(X + (m0 + row) * 256 + kc + k4 * 4);
            uint2 hi, lo; split4(v, hi, lo);
            uint32_t off = row * 128 + ((((uint32_t)(k4 >> 1)) ^ (row & 7)) << 4)
                         + (k4 & 1) * 8;
            *(uint2*)(sm + AHI + off) = hi;
            *(uint2*)(sm + ALO + off) = lo;
        }
        // ---- load W tile [64 rows x 64 k] ----
#pragma unroll
        for (int i = 0; i < 4; i++) {
            int lin = t + 256 * i;            // 0..1023
            int row = lin >> 4;               // 0..63
            int k4  = lin & 15;
            float4 v = *(const float4*)(W + row * 256 + kc + k4 * 4);
            uint2 hi, lo; split4(v, hi, lo);
            uint32_t off = row * 128 + ((((uint32_t)(k4 >> 1)) ^ (row & 7)) << 4)
                         + (k4 & 1) * 8;
            *(uint2*)(sm + BHI + off) = hi;
            *(uint2*)(sm + BLO + off) = lo;
        }
        __syncthreads();

#pragma unroll
        for (int ks = 0; ks < 4; ks++) {
            uint32_t ah[2][4], al[2][4], bh[2][4], bl[2][4];
#pragma unroll
            for (int mi = 0; mi < 2; mi++) {
                int row  = wm + mi * 16 + lr + (lm & 1) * 8;
                int unit = ks * 2 + (lm >> 1);
                uint32_t off = row * 128 + (((uint32_t)unit ^ (row & 7)) << 4);
                ldsm4(ah[mi], sbase + AHI + off);
                ldsm4(al[mi], sbase + ALO + off);
            }
#pragma unroll
            for (int bi = 0; bi < 2; bi++) {
                int n    = wn + bi * 16 + lr + (lm >> 1) * 8;
                int unit = ks * 2 + (lm & 1);
                uint32_t off = n * 128 + (((uint32_t)unit ^ (n & 7)) << 4);
                ldsm4(bh[bi], sbase + BHI + off);
                ldsm4(bl[bi], sbase + BLO + off);
            }
#pragma unroll
            for (int mi = 0; mi < 2; mi++) {
#pragma unroll
                for (int nf = 0; nf < 4; nf++) {
                    int bi = nf >> 1, hf = (nf & 1) * 2;
                    // hi*hi + hi*lo + lo*hi
                    mma16816(acc[mi][nf], ah[mi][0], ah[mi][1], ah[mi][2], ah[mi][3],
                             bh[bi][hf], bh[bi][hf + 1]);
                    mma16816(acc[mi][nf], ah[mi][0], ah[mi][1], ah[mi][2], ah[mi][3],
                             bl[bi][hf], bl[bi][hf + 1]);
                    mma16816(acc[mi][nf], al[mi][0], al[mi][1], al[mi][2], al[mi][3],
                             bh[bi][hf], bh[bi][hf + 1]);
                }
            }
        }
        __syncthreads();
    }

    // ---- epilogue ----
    const int rquad = lane >> 2;      // 0..7
    const int cpair = (lane & 3) * 2; // 0,2,4,6
#pragma unroll
    for (int mi = 0; mi < 2; mi++) {
#pragma unroll
        for (int nf = 0; nf < 4; nf++) {
            int colg = c0 + wn + nf * 8 + cpair;
#pragma unroll
            for (int half = 0; half < 2; half++) {
                int row = m0 + wm + mi * 16 + rquad + half * 8;
                float2 v = make_float2(acc[mi][nf][half * 2],
                                       acc[mi][nf][half * 2 + 1]);
                if (self) {
                    v.x += __ldg(bx + colg);
                    v.y += __ldg(bx + colg + 1);
                    *(float2*)(g_hpre + row * CCH + colg) = v;
                } else {
                    *(float2*)(g_yn + row * FF + (colg - 256)) = v;
                }
            }
        }
    }
}

// ---------------------------------------------------------------------------
// K2: gather-mean through shared memory.
// Block = (channel-chunk ct in 0..3, row-tile rt in 0..3, batch b in 0..7).
// smem: y_n[b, all 512 rows, 64 channels] (128KB) + idx tile (48KB).
// h_i[n,c] = (1/32) * sum_k y_n[idx_i[n,k], c] + bn[c]
// ---------------------------------------------------------------------------
__global__ __launch_bounds__(256) void k_gather(const int* __restrict__ i1,
                                                const int* __restrict__ i2,
                                                const int* __restrict__ i3,
                                                const float* __restrict__ bn) {
    extern __shared__ float smf[];
    float4* syn  = (float4*)smf;                 // 512 rows * 16 float4
    int*    sidx = (int*)(smf + 512 * 64);       // [3][128][32]

    const int t  = threadIdx.x;
    const int ct = blockIdx.x;   // 0..3 channel chunk (64 ch)
    const int rt = blockIdx.y;   // 0..3 output-row tile (128 rows)
    const int b  = blockIdx.z;   // 0..7

    const float4* yn4 = (const float4*)g_yn;
#pragma unroll
    for (int i = 0; i < 32; i++) {
        int lin = t + 256 * i;                  // = row*16 + c4
        int row = lin >> 4, c4 = lin & 15;
        syn[lin] = yn4[(b * 512 + row) * 64 + ct * 16 + c4];
    }
#pragma unroll
    for (int i = 0; i < 48; i++) {
        int lin = t + 256 * i;                  // 0..12287
        int s   = lin >> 12;
        int rem = lin & 4095;                   // rl*32 + k
        const int* ip = (s == 0) ? i1 : (s == 1) ? i2 : i3;
        sidx[lin] = ip[rt * 4096 + rem];
    }
    __syncthreads();

    const int cq = t & 15;     // which float4 of the 64-ch chunk
    const int rg = t >> 4;     // 16 rows in flight
    const float4 bias = ((const float4*)bn)[ct * 16 + cq];

    for (int r8 = 0; r8 < 8; r8++) {
        const int rl  = r8 * 16 + rg;
        const int row = b * 512 + rt * 128 + rl;
        for (int s = 0; s < 3; s++) {
            const int* ip = sidx + s * 4096 + rl * 32;
            float4 acc = make_float4(0.f, 0.f, 0.f, 0.f);
#pragma unroll
            for (int k = 0; k < 32; k++) {
                int j = ip[k];
                float4 v = syn[j * 16 + cq];
                acc.x += v.x; acc.y += v.y; acc.z += v.z; acc.w += v.w;
            }
            float4 o;
            o.x = acc.x * (1.f / 32.f) + bias.x;
            o.y = acc.y * (1.f / 32.f) + bias.y;
            o.z = acc.z * (1.f / 32.f) + bias.z;
            o.w = acc.w * (1.f / 32.f) + bias.w;
            ((float4*)g_hpre)[row * 256 + 64 + s * 64 + ct * 16 + cq] = o;
        }
    }
}

// ---------------------------------------------------------------------------
// K3: per-row L2 norm + per-channel BN partial sums, barrier-free main loop.
// One warp per row (4 rows per warp, 128 blocks x 8 warps).
// ---------------------------------------------------------------------------
__global__ __launch_bounds__(256) void k_stats() {
    __shared__ float ssum[CCH];
    __shared__ float ssq[CCH];
    const int t    = threadIdx.x;
    const int lane = t & 31;
    const int w    = t >> 5;

    for (int i = t; i < CCH; i += 256) { ssum[i] = 0.f; ssq[i] = 0.f; }
    __syncthreads();

    float4 cs[8], cq[8];
#pragma unroll
    for (int j = 0; j < 8; j++) {
        cs[j] = make_float4(0.f, 0.f, 0.f, 0.f);
        cq[j] = make_float4(0.f, 0.f, 0.f, 0.f);
    }

    const float4* hp4 = (const float4*)g_hpre;
#pragma unroll 1
    for (int ri = 0; ri < 4; ri++) {
        const int row = blockIdx.x * 32 + ri * 8 + w;
        const float4* rp = hp4 + row * 256;
        float4 v[8];
        float sq = 0.f;
#pragma unroll
        for (int j = 0; j < 8; j++) {
            v[j] = rp[lane + 32 * j];
            sq += v[j].x * v[j].x + v[j].y * v[j].y
                + v[j].z * v[j].z + v[j].w * v[j].w;
        }
#pragma unroll
        for (int o = 16; o; o >>= 1) sq += __shfl_xor_sync(0xffffffffu, sq, o);
        const float rn = 1.f / fmaxf(sqrtf(sq), 1e-12f);
        if (lane == 0) g_rnorm[row] = rn;
#pragma unroll
        for (int j = 0; j < 8; j++) {
            float h0 = fmaxf(v[j].x * rn, 0.f);
            float h1 = fmaxf(v[j].y * rn, 0.f);
            float h2 = fmaxf(v[j].z * rn, 0.f);
            float h3 = fmaxf(v[j].w * rn, 0.f);
            cs[j].x += h0; cq[j].x += h0 * h0;
            cs[j].y += h1; cq[j].y += h1 * h1;
            cs[j].z += h2; cq[j].z += h2 * h2;
            cs[j].w += h3; cq[j].w += h3 * h3;
        }
    }

#pragma unroll
    for (int j = 0; j < 8; j++) {
        const int c = 4 * (lane + 32 * j);
        atomicAdd(&ssum[c + 0], cs[j].x);
        atomicAdd(&ssum[c + 1], cs[j].y);
        atomicAdd(&ssum[c + 2], cs[j].z);
        atomicAdd(&ssum[c + 3], cs[j].w);
        atomicAdd(&ssq [c + 0], cq[j].x);
        atomicAdd(&ssq [c + 1], cq[j].y);
        atomicAdd(&ssq [c + 2], cq[j].z);
        atomicAdd(&ssq [c + 3], cq[j].w);
    }
    __syncthreads();

    for (int i = t; i < CCH; i += 256) {
        atomicAdd(&g_sum[i],   ssum[i]);
        atomicAdd(&g_sumsq[i], ssq[i]);
    }
}

// ---------------------------------------------------------------------------
// K4: finalize BN scale/shift per channel
// ---------------------------------------------------------------------------
__global__ void k_finalize(const float* __restrict__ gamma,
                           const float* __restrict__ beta) {
    int c = threadIdx.x;
    float mean = g_sum[c]   * (1.f / 4096.f);
    float var  = g_sumsq[c] * (1.f / 4096.f) - mean * mean;
    float sc   = gamma[c] * rsqrtf(var + 1e-5f);
    g_scale[c] = sc;
    g_shift[c] = beta[c] - mean * sc;
}

// ---------------------------------------------------------------------------
// K5: out = relu(h_pre * rnorm) * scale + shift. One block per row.
// ---------------------------------------------------------------------------
__global__ __launch_bounds__(256) void k_apply(float* __restrict__ out) {
    const int row = blockIdx.x;
    const int t   = threadIdx.x;
    const float4* hp4 = (const float4*)g_hpre;
    float4 v  = hp4[row * 256 + t];
    float  rn = g_rnorm[row];
    float4 sc = ((const float4*)g_scale)[t];
    float4 sh = ((const float4*)g_shift)[t];
    float4 o;
    o.x = fmaxf(v.x * rn, 0.f) * sc.x + sh.x;
    o.y = fmaxf(v.y * rn, 0.f) * sc.y + sh.y;
    o.z = fmaxf(v.z * rn, 0.f) * sc.z + sh.z;
    o.w = fmaxf(v.w * rn, 0.f) * sc.w + sh.w;
    ((float4*)out)[row * 256 + t] = o;
}

// ---------------------------------------------------------------------------
extern "C" void kernel_launch(void* const* d_in, const int* in_sizes, int n_in,
                              void* d_out, int out_size) {
    const float* x     = (const float*)d_in[0];
    const int*   i1    = (const int*)  d_in[1];
    const int*   i2    = (const int*)  d_in[2];
    const int*   i3    = (const int*)  d_in[3];
    const float* Wx    = (const float*)d_in[4];
    const float* bx    = (const float*)d_in[5];
    const float* Wn    = (const float*)d_in[6];
    const float* bnb   = (const float*)d_in[7];
    const float* gamma = (const float*)d_in[8];
    const float* beta  = (const float*)d_in[9];
    float* out = (float*)d_out;

    cudaFuncSetAttribute(k_gather, cudaFuncAttributeMaxDynamicSharedMemorySize,
                         180224);
    cudaFuncSetAttribute(k_gemm, cudaFuncAttributeMaxDynamicSharedMemorySize,
                         49152);

    k_zero<<<2, 1024>>>();
    k_gemm<<<dim3(8, 32), 256, 49152>>>(x, Wx, bx, Wn);
    k_gather<<<dim3(4, 4, 8), 256, 180224>>>(i1, i2, i3, bnb);
    k_stats<<<128, 256>>>();
    k_finalize<<<1, 1024>>>(gamma, beta);
    k_apply<<<4096, 256>>>(out);
}